// round 1
// baseline (speedup 1.0000x reference)
#include <cuda_runtime.h>

#define N_NODES 8192
#define CH      192
#define GW      1024      // padded group width for d2 rows
#define KNN     8

#define INFF __int_as_float(0x7f800000)

// ---------------- scratch (static device globals; no allocations) ----------
__device__ float g_xf [N_NODES * CH];      // node features [N, C]
__device__ float g_sq [N_NODES];           // squared norms
__device__ float g_d2 [N_NODES * GW];      // per-row distances within group (padded to 1024)
__device__ float g_tx1[N_NODES * CH];      // scaled-Laplacian aggregate
__device__ float g_dis[N_NODES];           // deg^{-1/2}
__device__ int   g_nbr[N_NODES * KNN];     // selected neighbor global indices
__device__ int   g_deg[N_NODES];           // in-neighbor counts

// ---------------- K1: NCHW -> [N, C] transpose ----------------------------
__global__ void transpose_kernel(const float* __restrict__ x) {
    __shared__ float tile[32][33];
    int b  = blockIdx.z;
    int c0 = blockIdx.y * 32;
    int p0 = blockIdx.x * 32;
    int tx = threadIdx.x, ty = threadIdx.y;
    // x[b][c][p] with p = h*32+w (1024 positions)
    tile[ty][tx] = x[((b * CH) + (c0 + ty)) * 1024 + p0 + tx];
    __syncthreads();
    g_xf[(b * 1024 + p0 + ty) * CH + c0 + tx] = tile[tx][ty];
}

// ---------------- K2: squared norms + zero degree --------------------------
__global__ void sqdeg_kernel() {
    int q    = blockIdx.x * 8 + (threadIdx.x >> 5);
    int lane = threadIdx.x & 31;
    const float* row = g_xf + q * CH;
    float s = 0.f;
    #pragma unroll
    for (int c = lane; c < CH; c += 32) { float v = row[c]; s += v * v; }
    #pragma unroll
    for (int o = 16; o; o >>= 1) s += __shfl_xor_sync(0xffffffffu, s, o);
    if (lane == 0) { g_sq[q] = s; g_deg[q] = 0; }
}

// ---------------- K3: per-group pairwise d2 GEMM (128x128 tile, 8x8/thread)
__global__ __launch_bounds__(256) void knn_d2_kernel() {
    __shared__ float As[16][132];
    __shared__ float Bs[16][132];

    int g      = blockIdx.z;
    int gStart = g << 10;
    int gSize  = (g == 7) ? 1023 : 1024;
    int m0 = blockIdx.y * 128;
    int n0 = blockIdx.x * 128;

    int t  = threadIdx.x;
    int tx = t & 15;        // n direction
    int ty = t >> 4;        // m direction

    float acc[8][8];
    #pragma unroll
    for (int i = 0; i < 8; i++)
        #pragma unroll
        for (int j = 0; j < 8; j++) acc[i][j] = 0.f;

    int lm = t >> 1;              // 0..127 : tile row loaded by this thread
    int lk = (t & 1) * 8;         // 0 or 8 : k offset
    const float* Arow = g_xf + (gStart + m0 + lm) * CH + lk;
    const float* Brow = g_xf + (gStart + n0 + lm) * CH + lk;

    for (int k0 = 0; k0 < CH; k0 += 16) {
        float4 a0 = *(const float4*)(Arow + k0);
        float4 a1 = *(const float4*)(Arow + k0 + 4);
        float4 b0 = *(const float4*)(Brow + k0);
        float4 b1 = *(const float4*)(Brow + k0 + 4);
        __syncthreads();
        As[lk + 0][lm] = a0.x; As[lk + 1][lm] = a0.y;
        As[lk + 2][lm] = a0.z; As[lk + 3][lm] = a0.w;
        As[lk + 4][lm] = a1.x; As[lk + 5][lm] = a1.y;
        As[lk + 6][lm] = a1.z; As[lk + 7][lm] = a1.w;
        Bs[lk + 0][lm] = b0.x; Bs[lk + 1][lm] = b0.y;
        Bs[lk + 2][lm] = b0.z; Bs[lk + 3][lm] = b0.w;
        Bs[lk + 4][lm] = b1.x; Bs[lk + 5][lm] = b1.y;
        Bs[lk + 6][lm] = b1.z; Bs[lk + 7][lm] = b1.w;
        __syncthreads();
        #pragma unroll
        for (int kk = 0; kk < 16; kk++) {
            float4 av0 = *(const float4*)&As[kk][ty * 4];
            float4 av1 = *(const float4*)&As[kk][64 + ty * 4];
            float4 bv0 = *(const float4*)&Bs[kk][tx * 4];
            float4 bv1 = *(const float4*)&Bs[kk][64 + tx * 4];
            float av[8] = {av0.x, av0.y, av0.z, av0.w, av1.x, av1.y, av1.z, av1.w};
            float bv[8] = {bv0.x, bv0.y, bv0.z, bv0.w, bv1.x, bv1.y, bv1.z, bv1.w};
            #pragma unroll
            for (int i = 0; i < 8; i++)
                #pragma unroll
                for (int j = 0; j < 8; j++)
                    acc[i][j] += av[i] * bv[j];
        }
    }

    // epilogue: d2 = sq[m] + sq[n] - 2*dot, mask self + group padding
    float sqm[8], sqn[8];
    #pragma unroll
    for (int i = 0; i < 8; i++) {
        int mr = (i < 4) ? (ty * 4 + i) : (64 + ty * 4 + i - 4);
        int nc = (i < 4) ? (tx * 4 + i) : (64 + tx * 4 + i - 4);
        sqm[i] = g_sq[gStart + m0 + mr];
        sqn[i] = g_sq[gStart + n0 + nc];
    }
    #pragma unroll
    for (int i = 0; i < 8; i++) {
        int mm = m0 + ((i < 4) ? (ty * 4 + i) : (64 + ty * 4 + i - 4));
        #pragma unroll
        for (int j = 0; j < 8; j++) {
            int nn = n0 + ((j < 4) ? (tx * 4 + j) : (64 + tx * 4 + j - 4));
            float v = sqm[i] + sqn[j] - 2.f * acc[i][j];
            if (nn >= gSize || nn == mm) v = INFF;
            g_d2[(gStart + mm) * GW + nn] = v;
        }
    }
}

// ---------------- K4: warp-per-row top-8 (lexicographic (val, idx)) --------
__global__ void topk_kernel() {
    int q    = blockIdx.x * 8 + (threadIdx.x >> 5);
    int lane = threadIdx.x & 31;

    if (q == N_NODES - 1) {               // singleton batch-8 node: no edges
        if (lane < KNN) g_nbr[q * KNN + lane] = 0;
        return;
    }
    int g      = q >> 10;                 // valid for q <= 8190
    int gStart = g << 10;
    const float* row = g_d2 + q * GW;

    float v[8]; int id[8];
    #pragma unroll
    for (int s = 0; s < 8; s++) { v[s] = INFF; id[s] = 1 << 30; }

    for (int jl = lane; jl < GW; jl += 32) {
        float d = fmaxf(row[jl], 0.0f);
        if (d < v[7]) {
            v[7] = d; id[7] = jl;
            #pragma unroll
            for (int s = 7; s > 0; s--) {
                if (v[s] < v[s - 1]) {
                    float tv = v[s]; v[s] = v[s - 1]; v[s - 1] = tv;
                    int   ti = id[s]; id[s] = id[s - 1]; id[s - 1] = ti;
                }
            }
        }
    }

    // merge 32 sorted 8-lists: 8 rounds of warp-min over (val, idx) keys
    #pragma unroll
    for (int r = 0; r < KNN; r++) {
        unsigned long long key =
            ((unsigned long long)__float_as_uint(v[0]) << 32) | (unsigned)id[0];
        unsigned long long best = key;
        #pragma unroll
        for (int o = 16; o; o >>= 1) {
            unsigned long long other = __shfl_xor_sync(0xffffffffu, best, o);
            best = (other < best) ? other : best;
        }
        if (key == best) {                // unique owner (idx is unique)
            int j = gStart + (int)(best & 0xffffffffu);
            g_nbr[q * KNN + r] = j;
            atomicAdd(&g_deg[j], 1);
            #pragma unroll
            for (int s = 0; s < 7; s++) { v[s] = v[s + 1]; id[s] = id[s + 1]; }
            v[7] = INFF; id[7] = 1 << 30;
        }
    }
}

// ---------------- K5: dis = deg^{-1/2} --------------------------------------
__global__ void dis_kernel() {
    int i = blockIdx.x * 256 + threadIdx.x;
    if (i < N_NODES) {
        int d = g_deg[i];
        g_dis[i] = (d > 0) ? rsqrtf((float)d) : 0.0f;
    }
}

// ---------------- K6: Tx1[q] = -dis[q] * sum_j dis[j] * xf[j] ---------------
__global__ void tx1_kernel() {
    int q = blockIdx.x;
    int c = threadIdx.x;
    float dq = g_dis[q];
    float s = 0.f;
    #pragma unroll
    for (int e = 0; e < KNN; e++) {
        int j = g_nbr[q * KNN + e];
        s += g_dis[j] * g_xf[j * CH + c];
    }
    g_tx1[q * CH + c] = -dq * s;
}

// ---------------- K7: out = xf@W0 + tx1@W1 + bias (128x64 tile, 8x4/thr) ---
__global__ __launch_bounds__(256) void out_gemm_kernel(
    const float* __restrict__ W0, const float* __restrict__ W1,
    const float* __restrict__ bias, float* __restrict__ out)
{
    __shared__ float As[16][132];
    __shared__ float Bs[16][68];

    int m0 = blockIdx.y * 128;
    int n0 = blockIdx.x * 64;
    int t  = threadIdx.x;
    int tx = t & 15;        // n
    int ty = t >> 4;        // m

    float acc[8][4];
    #pragma unroll
    for (int i = 0; i < 8; i++)
        #pragma unroll
        for (int j = 0; j < 4; j++) acc[i][j] = 0.f;

    int lm  = t >> 1;            // A tile row 0..127
    int lk  = (t & 1) * 8;
    int lkb = t >> 4;            // B tile k row 0..15
    int ln  = (t & 15) * 4;      // B tile col

    #pragma unroll
    for (int ph = 0; ph < 2; ph++) {
        const float* A = ph ? g_tx1 : g_xf;
        const float* W = ph ? W1 : W0;
        for (int k0 = 0; k0 < CH; k0 += 16) {
            float4 a0 = *(const float4*)&A[(m0 + lm) * CH + k0 + lk];
            float4 a1 = *(const float4*)&A[(m0 + lm) * CH + k0 + lk + 4];
            float4 w  = *(const float4*)&W[(k0 + lkb) * CH + n0 + ln];
            __syncthreads();
            As[lk + 0][lm] = a0.x; As[lk + 1][lm] = a0.y;
            As[lk + 2][lm] = a0.z; As[lk + 3][lm] = a0.w;
            As[lk + 4][lm] = a1.x; As[lk + 5][lm] = a1.y;
            As[lk + 6][lm] = a1.z; As[lk + 7][lm] = a1.w;
            *(float4*)&Bs[lkb][ln] = w;
            __syncthreads();
            #pragma unroll
            for (int kk = 0; kk < 16; kk++) {
                float4 av0 = *(const float4*)&As[kk][ty * 4];
                float4 av1 = *(const float4*)&As[kk][64 + ty * 4];
                float4 bv  = *(const float4*)&Bs[kk][tx * 4];
                float av[8] = {av0.x, av0.y, av0.z, av0.w, av1.x, av1.y, av1.z, av1.w};
                float b4[4] = {bv.x, bv.y, bv.z, bv.w};
                #pragma unroll
                for (int i = 0; i < 8; i++)
                    #pragma unroll
                    for (int j = 0; j < 4; j++)
                        acc[i][j] += av[i] * b4[j];
            }
        }
    }

    #pragma unroll
    for (int i = 0; i < 8; i++) {
        int m = m0 + ((i < 4) ? (ty * 4 + i) : (64 + ty * 4 + i - 4));
        #pragma unroll
        for (int j = 0; j < 4; j++) {
            int n = n0 + tx * 4 + j;
            out[m * CH + n] = acc[i][j] + bias[n];
        }
    }
}

// ---------------- launch -----------------------------------------------------
extern "C" void kernel_launch(void* const* d_in, const int* in_sizes, int n_in,
                              void* d_out, int out_size) {
    const float* x    = (const float*)d_in[0];   // [8,192,32,32]
    const float* W0   = (const float*)d_in[1];   // [192,192]
    const float* W1   = (const float*)d_in[2];   // [192,192]
    const float* bias = (const float*)d_in[3];   // [192]
    float* out = (float*)d_out;                  // [8192,192]

    transpose_kernel<<<dim3(32, 6, 8), dim3(32, 32)>>>(x);
    sqdeg_kernel<<<1024, 256>>>();
    knn_d2_kernel<<<dim3(8, 8, 8), 256>>>();
    topk_kernel<<<1024, 256>>>();
    dis_kernel<<<32, 256>>>();
    tx1_kernel<<<8192, 192>>>();
    out_gemm_kernel<<<dim3(3, 64), 256>>>(W0, W1, bias, out);
}